// round 15
// baseline (speedup 1.0000x reference)
#include <cuda_runtime.h>
#include <cuda_fp16.h>
#include <math.h>
#include <stdint.h>

#define BB 16
#define NN 768
#define EE 1024
#define HH 16
#define DD 64
// mask addend in log2 domain: -1e16 * log2(e)
#define NEGV2 (-1.4426950e16f)

// Scratch (static device globals; no runtime allocation allowed). All fp16.
__device__ __half g_qh[BB * HH * NN * DD];   // (B,H,N,D), pre-scaled by log2e/32
__device__ __half g_kh[BB * HH * NN * DD];
__device__ __half g_vh[BB * HH * NN * DD];
__device__ __half g_attn[BB * NN * EE];      // (B,N,E) pre-final-projection
__device__ __half g_wtf[EE * EE];            // fp16 Wf

// ---------------------------------------------------------------------------
// helpers
// ---------------------------------------------------------------------------
__device__ __forceinline__ float ex2(float x) {
    float y;
    asm("ex2.approx.f32 %0, %1;" : "=f"(y) : "f"(x));
    return y;
}
__device__ __forceinline__ uint32_t pack2(float x, float y) {
    __half2 h = __floats2half2_rn(x, y);
    return *(uint32_t*)&h;
}
__device__ __forceinline__ void mma_f16(float d[4],
                                        uint32_t a0, uint32_t a1, uint32_t a2, uint32_t a3,
                                        uint32_t b0, uint32_t b1) {
    asm volatile(
        "mma.sync.aligned.m16n8k16.row.col.f32.f16.f16.f32 "
        "{%0,%1,%2,%3}, {%4,%5,%6,%7}, {%8,%9}, {%0,%1,%2,%3};\n"
        : "+f"(d[0]), "+f"(d[1]), "+f"(d[2]), "+f"(d[3])
        : "r"(a0), "r"(a1), "r"(a2), "r"(a3), "r"(b0), "r"(b1));
}
#define LDSM4(r0, r1, r2, r3, addr) \
    asm volatile("ldmatrix.sync.aligned.m8n8.x4.shared.b16 {%0,%1,%2,%3}, [%4];" \
                 : "=r"(r0), "=r"(r1), "=r"(r2), "=r"(r3) : "r"(addr))
#define LDSM4T(r0, r1, r2, r3, addr) \
    asm volatile("ldmatrix.sync.aligned.m8n8.x4.trans.shared.b16 {%0,%1,%2,%3}, [%4];" \
                 : "=r"(r0), "=r"(r1), "=r"(r2), "=r"(r3) : "r"(addr))

__device__ __forceinline__ void cp16(void* smem, const void* gmem) {
    uint32_t s = (uint32_t)__cvta_generic_to_shared(smem);
    asm volatile("cp.async.cg.shared.global [%0], [%1], 16;\n" :: "r"(s), "l"(gmem));
}
__device__ __forceinline__ void cp_commit() { asm volatile("cp.async.commit_group;\n"); }
__device__ __forceinline__ void cp_wait0() { asm volatile("cp.async.wait_group 0;\n"); }

// ---------------------------------------------------------------------------
// Stage A (merged): per-head projections via fp16 mma + Wf->fp16 prepass.
// grid (6, 256, 4), block 256, __launch_bounds__(256, 5) for occupancy.
// Q output scaled by log2e/sqrt(E) so attn softmax uses raw ex2.
// smem (halves): Xh[128][72] | Wh[64][72]  = 27648 B
// ---------------------------------------------------------------------------
#define PXH(r, c_) psm[(r) * 72 + (c_)]
#define PWH(r, c_) psm[9216 + (r) * 72 + (c_)]

__global__ __launch_bounds__(256, 5) void proj_mma_kernel(
    const float* __restrict__ q, const float* __restrict__ k, const float* __restrict__ v,
    const float* __restrict__ Wq, const float* __restrict__ Wk, const float* __restrict__ Wv,
    const float* __restrict__ Wf)
{
    extern __shared__ __half psm[];
    const int which = blockIdx.z;
    const int tid = threadIdx.x;

    if (which == 3) {
        // Wf -> fp16, 8 elements per thread
        const int gid = (blockIdx.y * 6 + blockIdx.x) * 256 + tid;
        if (gid < EE * EE / 8) {
            const float4 v0 = *(const float4*)(Wf + (size_t)gid * 8);
            const float4 v1 = *(const float4*)(Wf + (size_t)gid * 8 + 4);
            __half2 h[4];
            h[0] = __floats2half2_rn(v0.x, v0.y);
            h[1] = __floats2half2_rn(v0.z, v0.w);
            h[2] = __floats2half2_rn(v1.x, v1.y);
            h[3] = __floats2half2_rn(v1.z, v1.w);
            *(float4*)(g_wtf + (size_t)gid * 8) = *(float4*)h;
        }
        return;
    }

    const float* X = (which == 0) ? q : (which == 1) ? k : v;
    const float* W = (which == 0) ? Wq : (which == 1) ? Wk : Wv;
    __half* Y = (which == 0) ? g_qh : (which == 1) ? g_kh : g_vh;
    const float oscl = (which == 0) ? (0.03125f * 1.44269504f) : 1.0f;

    const int bh = blockIdx.y;
    const int b = bh >> 4, h = bh & 15;
    const int n0 = blockIdx.x * 128;

    // stage X (128x64) and W (64x64) as fp16
    {
        const int rr = tid >> 4;
        const int c4 = (tid & 15) * 4;
        const float* src = X + ((size_t)b * NN + n0) * EE + h * DD;
        #pragma unroll
        for (int i = 0; i < 8; i++) {
            const int row = rr + 16 * i;
            float4 vv = *(const float4*)(src + (size_t)row * EE + c4);
            __half2 h2[2] = {__floats2half2_rn(vv.x, vv.y), __floats2half2_rn(vv.z, vv.w)};
            *(float2*)&PXH(row, c4) = *(float2*)h2;
        }
        const float* wsrc = W + h * DD * DD;
        #pragma unroll
        for (int i = 0; i < 4; i++) {
            const int row = rr + 16 * i;
            float4 wv = *(const float4*)(wsrc + row * DD + c4);
            __half2 h2[2] = {__floats2half2_rn(wv.x, wv.y), __floats2half2_rn(wv.z, wv.w)};
            *(float2*)&PWH(row, c4) = *(float2*)h2;
        }
    }
    __syncthreads();

    const int w = tid >> 5;
    const int lane = tid & 31;
    const int g = lane >> 2;
    const int qd = lane & 3;
    const int qrow = 16 * w + g;

    float acc[8][4] = {};
    #pragma unroll
    for (int kk = 0; kk < 4; kk++) {
        uint32_t a0 = *(uint32_t*)&PXH(qrow,     kk * 16 + 2 * qd);
        uint32_t a1 = *(uint32_t*)&PXH(qrow + 8, kk * 16 + 2 * qd);
        uint32_t a2 = *(uint32_t*)&PXH(qrow,     kk * 16 + 2 * qd + 8);
        uint32_t a3 = *(uint32_t*)&PXH(qrow + 8, kk * 16 + 2 * qd + 8);
        #pragma unroll
        for (int nt = 0; nt < 8; nt++) {
            uint32_t b0 = *(uint32_t*)&PWH(nt * 8 + g, kk * 16 + 2 * qd);
            uint32_t b1 = *(uint32_t*)&PWH(nt * 8 + g, kk * 16 + 2 * qd + 8);
            mma_f16(acc[nt], a0, a1, a2, a3, b0, b1);
        }
    }

    __half* dst = Y + (((size_t)bh) * NN + n0 + 16 * w) * DD;
    #pragma unroll
    for (int nt = 0; nt < 8; nt++) {
        const int col = nt * 8 + 2 * qd;
        *(__half2*)(dst + (size_t)g * DD + col) =
            __floats2half2_rn(acc[nt][0] * oscl, acc[nt][1] * oscl);
        *(__half2*)(dst + (size_t)(g + 8) * DD + col) =
            __floats2half2_rn(acc[nt][2] * oscl, acc[nt][3] * oscl);
    }
}

// ---------------------------------------------------------------------------
// Stage B: flash attention, fp16 mma m16n8k16, ktile=64 sync staging,
// log2-domain softmax, deferred l-reduction, ALL fragment feeds via ldmatrix.
// grid (6, 256), block 256, dynamic smem 39936 B, 2 CTAs/SM.
// smem (halves): Qs[128][72] | Ks[64][72] | Vs[64][72] | madd[768] (floats)
// ---------------------------------------------------------------------------
#define QH(r, c_) smh[(r) * 72 + (c_)]
#define KH(r, c_) smh[9216 + (r) * 72 + (c_)]
#define VH(r, c_) smh[13824 + (r) * 72 + (c_)]

__global__ __launch_bounds__(256, 2) void attn_f16_kernel(const float* __restrict__ mask)
{
    extern __shared__ __half smh[];
    float* madd = (float*)(smh + 18432);

    const int bh = blockIdx.y;
    const int b = bh >> 4, h = bh & 15;
    const int q0 = blockIdx.x * 128;
    const int tid = threadIdx.x;
    const int w = tid >> 5;
    const int lane = tid & 31;
    const int g = lane >> 2;
    const int qd = lane & 3;

    for (int i = tid; i < NN; i += 256)
        madd[i] = (mask[h * NN + i] == -INFINITY) ? NEGV2 : 0.f;

    const __half* qb = g_qh + ((size_t)bh * NN + q0) * DD;
    const __half* kb = g_kh + ((size_t)bh * NN) * DD;
    const __half* vb = g_vh + ((size_t)bh * NN) * DD;

    {
        const int rr = tid >> 3, c8 = (tid & 7) * 8;
        #pragma unroll
        for (int i = 0; i < 4; i++)
            *(float4*)&QH(rr + 32 * i, c8) =
                *(const float4*)(qb + (size_t)(rr + 32 * i) * DD + c8);
    }
    __syncthreads();

    const int qrow = 16 * w + g;
    const float addq0 = madd[q0 + qrow];
    const float addq1 = madd[q0 + qrow + 8];

    float m0r = -INFINITY, m1r = -INFINITY;
    float l0 = 0.f, l1 = 0.f;          // per-thread partials; reduced at end
    float o[8][4] = {};

    // ldmatrix address bases
    const uint32_t smbh = (uint32_t)__cvta_generic_to_shared(smh);
    const int sq = lane >> 3, rp = lane & 7;
    // Q A-frag 16x16 tiles: rows 16w + (sq&1)*8 + rp, col (sq>>1)*8
    const uint32_t aQ = smbh + 2u * ((16 * w + (sq & 1) * 8 + rp) * 72 + (sq >> 1) * 8);
    // K B-frag 16x16 tiles (nt-pairs): rows ntp*16 + (sq&1)*8 + rp
    uint32_t aK[4];
    #pragma unroll
    for (int p = 0; p < 4; p++)
        aK[p] = smbh + 2u * (9216 + (p * 16 + (sq & 1) * 8 + rp) * 72 + (sq >> 1) * 8);
    // V B-frags via trans-LDSM (k-rows x d-cols)
    uint32_t aV[4];
    #pragma unroll
    for (int dp = 0; dp < 4; dp++)
        aV[dp] = smbh + 2u * (13824 + ((sq & 1) * 8 + rp) * 72
                              + dp * 16 + (sq >> 1) * 8);

    for (int kt = 0; kt < NN; kt += 64) {
        __syncthreads();
        {
            const int rr = tid >> 3, c8 = (tid & 7) * 8;
            #pragma unroll
            for (int i = 0; i < 2; i++) {
                *(float4*)&KH(rr + 32 * i, c8) =
                    *(const float4*)(kb + (size_t)(kt + rr + 32 * i) * DD + c8);
                *(float4*)&VH(rr + 32 * i, c8) =
                    *(const float4*)(vb + (size_t)(kt + rr + 32 * i) * DD + c8);
            }
        }
        __syncthreads();

        // S = Q K^T  (A and K fragments via ldmatrix.x4)
        float s[8][4] = {};
        #pragma unroll
        for (int kk = 0; kk < 4; kk++) {
            uint32_t a0, a1, a2, a3;
            LDSM4(a0, a1, a2, a3, aQ + kk * 32u);
            #pragma unroll
            for (int p = 0; p < 4; p++) {
                uint32_t b0e, b0o, b1e, b1o;
                LDSM4(b0e, b0o, b1e, b1o, aK[p] + kk * 32u);
                mma_f16(s[2 * p],     a0, a1, a2, a3, b0e, b1e);
                mma_f16(s[2 * p + 1], a0, a1, a2, a3, b0o, b1o);
            }
        }

        // mask + online softmax (log2 domain); max must be quad-uniform
        float pm0 = -INFINITY, pm1 = -INFINITY;
        #pragma unroll
        for (int nt = 0; nt < 8; nt++) {
            float2 mk = *(const float2*)&madd[kt + nt * 8 + 2 * qd];
            s[nt][0] += fmaxf(addq0 + mk.x, NEGV2);
            s[nt][1] += fmaxf(addq0 + mk.y, NEGV2);
            s[nt][2] += fmaxf(addq1 + mk.x, NEGV2);
            s[nt][3] += fmaxf(addq1 + mk.y, NEGV2);
            pm0 = fmaxf(pm0, fmaxf(s[nt][0], s[nt][1]));
            pm1 = fmaxf(pm1, fmaxf(s[nt][2], s[nt][3]));
        }
        pm0 = fmaxf(pm0, __shfl_xor_sync(0xffffffffu, pm0, 1));
        pm0 = fmaxf(pm0, __shfl_xor_sync(0xffffffffu, pm0, 2));
        pm1 = fmaxf(pm1, __shfl_xor_sync(0xffffffffu, pm1, 1));
        pm1 = fmaxf(pm1, __shfl_xor_sync(0xffffffffu, pm1, 2));

        const float mn0 = fmaxf(m0r, pm0), mn1 = fmaxf(m1r, pm1);
        const float corr0 = ex2(m0r - mn0), corr1 = ex2(m1r - mn1);
        m0r = mn0; m1r = mn1;

        float rs0 = 0.f, rs1 = 0.f;
        #pragma unroll
        for (int nt = 0; nt < 8; nt++) {
            s[nt][0] = ex2(s[nt][0] - mn0); rs0 += s[nt][0];
            s[nt][1] = ex2(s[nt][1] - mn0); rs0 += s[nt][1];
            s[nt][2] = ex2(s[nt][2] - mn1); rs1 += s[nt][2];
            s[nt][3] = ex2(s[nt][3] - mn1); rs1 += s[nt][3];
        }
        l0 = l0 * corr0 + rs0;
        l1 = l1 * corr1 + rs1;

        #pragma unroll
        for (int dt = 0; dt < 8; dt++) {
            o[dt][0] *= corr0; o[dt][1] *= corr0;
            o[dt][2] *= corr1; o[dt][3] *= corr1;
        }

        // pack P C-fragments into A-fragments (direct register feed)
        uint32_t ph[8][2];
        #pragma unroll
        for (int nt = 0; nt < 8; nt++) {
            ph[nt][0] = pack2(s[nt][0], s[nt][1]);
            ph[nt][1] = pack2(s[nt][2], s[nt][3]);
        }

        // O += P V  (V B-fragments via ldmatrix.x4.trans)
        #pragma unroll
        for (int kk = 0; kk < 4; kk++) {
            uint32_t a0 = ph[2 * kk][0];
            uint32_t a1 = ph[2 * kk][1];
            uint32_t a2 = ph[2 * kk + 1][0];
            uint32_t a3 = ph[2 * kk + 1][1];
            #pragma unroll
            for (int dp = 0; dp < 4; dp++) {
                uint32_t b0, b1, b2, b3;
                LDSM4T(b0, b1, b2, b3, aV[dp] + kk * 2304u);
                mma_f16(o[2 * dp],     a0, a1, a2, a3, b0, b1);
                mma_f16(o[2 * dp + 1], a0, a1, a2, a3, b2, b3);
            }
        }
    }

    // final quad reduction of l partials
    l0 += __shfl_xor_sync(0xffffffffu, l0, 1);
    l0 += __shfl_xor_sync(0xffffffffu, l0, 2);
    l1 += __shfl_xor_sync(0xffffffffu, l1, 1);
    l1 += __shfl_xor_sync(0xffffffffu, l1, 2);

    const float inv0 = 1.f / l0, inv1 = 1.f / l1;
    __half* ob = g_attn + ((size_t)b * NN + q0 + 16 * w) * EE + h * DD;
    #pragma unroll
    for (int dt = 0; dt < 8; dt++) {
        const int col = dt * 8 + 2 * qd;
        *(__half2*)(ob + (size_t)g * EE + col) =
            __floats2half2_rn(o[dt][0] * inv0, o[dt][1] * inv0);
        *(__half2*)(ob + (size_t)(g + 8) * EE + col) =
            __floats2half2_rn(o[dt][2] * inv1, o[dt][3] * inv1);
    }
}

// ---------------------------------------------------------------------------
// Stage C: out = g_attn @ Wf^T, fp16 mma m16n8k16. 128x128x64(halves) chunks,
// 2-stage cp.async pipeline, ldmatrix fragment feeds.
// grid (8, 96), block 256, smem 73728 B.
// smem (halves): As[2][128][72] | Ws[2][128][72]
// ---------------------------------------------------------------------------
#define ASH(bf, r, c_) smh[(bf) * 9216 + (r) * 72 + (c_)]
#define WSH(bf, r, c_) smh[18432 + (bf) * 9216 + (r) * 72 + (c_)]

__global__ __launch_bounds__(256, 2) void gemm_f16_kernel(float* __restrict__ out)
{
    extern __shared__ __half smh[];

    const int e0 = blockIdx.x * 128;
    const int m0 = blockIdx.y * 128;
    const int tid = threadIdx.x;
    const int w = tid >> 5;
    const int lane = tid & 31;
    const int g = lane >> 2, qd = lane & 3;
    const int mb = (w & 1) * 64;
    const int nb = (w >> 1) * 32;

    const __half* Ab = g_attn + (size_t)m0 * EE;
    const __half* Wb = g_wtf + (size_t)e0 * EE;

    const int rr = tid >> 3;           // 0..31
    const int c8 = (tid & 7) * 8;      // half col of 16B piece

    // ldmatrix address bases (buffer 0); buffer stride = 18432 B (9216 halves)
    const uint32_t smbh = (uint32_t)__cvta_generic_to_shared(smh);
    const int sq = lane >> 3, rp = lane & 7;
    uint32_t aA[4], aB[2];
    #pragma unroll
    for (int mt = 0; mt < 4; mt++)
        aA[mt] = smbh + 2u * ((mb + mt * 16 + (sq & 1) * 8 + rp) * 72 + (sq >> 1) * 8);
    #pragma unroll
    for (int p = 0; p < 2; p++)
        aB[p] = smbh + 2u * (18432 + (nb + p * 16 + (sq & 1) * 8 + rp) * 72 + (sq >> 1) * 8);

    float acc[4][4][4] = {};

    #pragma unroll
    for (int i = 0; i < 4; i++) {
        cp16(&ASH(0, rr + 32 * i, c8), Ab + (size_t)(rr + 32 * i) * EE + c8);
        cp16(&WSH(0, rr + 32 * i, c8), Wb + (size_t)(rr + 32 * i) * EE + c8);
    }
    cp_commit();

    for (int it = 0; it < EE / 64; it++) {
        const int buf = it & 1;
        const uint32_t boff = buf * 18432u;
        cp_wait0();
        __syncthreads();

        if (it + 1 < EE / 64) {
            const int kc = (it + 1) * 64;
            #pragma unroll
            for (int i = 0; i < 4; i++) {
                cp16(&ASH(buf ^ 1, rr + 32 * i, c8),
                     Ab + (size_t)(rr + 32 * i) * EE + kc + c8);
                cp16(&WSH(buf ^ 1, rr + 32 * i, c8),
                     Wb + (size_t)(rr + 32 * i) * EE + kc + c8);
            }
            cp_commit();
        }

        #pragma unroll
        for (int kk = 0; kk < 4; kk++) {
            uint32_t a[4][4];
            #pragma unroll
            for (int mt = 0; mt < 4; mt++)
                LDSM4(a[mt][0], a[mt][1], a[mt][2], a[mt][3], aA[mt] + boff + kk * 32u);
            #pragma unroll
            for (int p = 0; p < 2; p++) {
                uint32_t b0e, b0o, b1e, b1o;
                LDSM4(b0e, b0o, b1e, b1o, aB[p] + boff + kk * 32u);
                #pragma unroll
                for (int mt = 0; mt < 4; mt++) {
                    mma_f16(acc[mt][2 * p],     a[mt][0], a[mt][1], a[mt][2], a[mt][3], b0e, b1e);
                    mma_f16(acc[mt][2 * p + 1], a[mt][0], a[mt][1], a[mt][2], a[mt][3], b0o, b1o);
                }
            }
        }
    }

    #pragma unroll
    for (int mt = 0; mt < 4; mt++) {
        const int row0 = m0 + mb + mt * 16 + g;
        #pragma unroll
        for (int nt = 0; nt < 4; nt++) {
            const int col = e0 + nb + nt * 8 + 2 * qd;
            *(float2*)(out + (size_t)row0 * EE + col) =
                make_float2(acc[mt][nt][0], acc[mt][nt][1]);
            *(float2*)(out + (size_t)(row0 + 8) * EE + col) =
                make_float2(acc[mt][nt][2], acc[mt][nt][3]);
        }
    }
}

// ---------------------------------------------------------------------------
extern "C" void kernel_launch(void* const* d_in, const int* in_sizes, int n_in,
                              void* d_out, int out_size)
{
    const float* q    = (const float*)d_in[0];
    const float* k    = (const float*)d_in[1];
    const float* v    = (const float*)d_in[2];
    const float* mask = (const float*)d_in[3];
    const float* Wq   = (const float*)d_in[4];
    const float* Wk   = (const float*)d_in[5];
    const float* Wv   = (const float*)d_in[6];
    const float* Wf   = (const float*)d_in[7];
    float* out = (float*)d_out;

    const int proj_smem = (128 * 72 + 64 * 72) * 2;   // 27648
    const int attn_smem = 18432 * 2 + 768 * 4;        // 39936
    const int gemm_smem = 36864 * 2;                  // 73728
    cudaFuncSetAttribute(proj_mma_kernel,
                         cudaFuncAttributeMaxDynamicSharedMemorySize, proj_smem);
    cudaFuncSetAttribute(attn_f16_kernel,
                         cudaFuncAttributeMaxDynamicSharedMemorySize, attn_smem);
    cudaFuncSetAttribute(gemm_f16_kernel,
                         cudaFuncAttributeMaxDynamicSharedMemorySize, gemm_smem);

    proj_mma_kernel<<<dim3(NN / 128, BB * HH, 4), 256, proj_smem>>>(
        q, k, v, Wq, Wk, Wv, Wf);
    attn_f16_kernel<<<dim3(NN / 128, BB * HH), 256, attn_smem>>>(mask);
    gemm_f16_kernel<<<dim3(EE / 128, (BB * NN) / 128), 256, gemm_smem>>>(out);
}

// round 16
// speedup vs baseline: 1.0127x; 1.0127x over previous
#include <cuda_runtime.h>
#include <cuda_fp16.h>
#include <math.h>
#include <stdint.h>

#define BB 16
#define NN 768
#define EE 1024
#define HH 16
#define DD 64
// mask addend in log2 domain: -1e16 * log2(e)
#define NEGV2 (-1.4426950e16f)

// Scratch (static device globals; no runtime allocation allowed). All fp16.
__device__ __half g_qh[BB * HH * NN * DD];   // (B,H,N,D), pre-scaled by log2e/32
__device__ __half g_kh[BB * HH * NN * DD];
__device__ __half g_vh[BB * HH * NN * DD];
__device__ __half g_attn[BB * NN * EE];      // (B,N,E) pre-final-projection
__device__ __half g_wtf[EE * EE];            // fp16 Wf

// ---------------------------------------------------------------------------
// helpers
// ---------------------------------------------------------------------------
__device__ __forceinline__ float ex2(float x) {
    float y;
    asm("ex2.approx.f32 %0, %1;" : "=f"(y) : "f"(x));
    return y;
}
__device__ __forceinline__ uint32_t pack2(float x, float y) {
    __half2 h = __floats2half2_rn(x, y);
    return *(uint32_t*)&h;
}
__device__ __forceinline__ void mma_f16(float d[4],
                                        uint32_t a0, uint32_t a1, uint32_t a2, uint32_t a3,
                                        uint32_t b0, uint32_t b1) {
    asm volatile(
        "mma.sync.aligned.m16n8k16.row.col.f32.f16.f16.f32 "
        "{%0,%1,%2,%3}, {%4,%5,%6,%7}, {%8,%9}, {%0,%1,%2,%3};\n"
        : "+f"(d[0]), "+f"(d[1]), "+f"(d[2]), "+f"(d[3])
        : "r"(a0), "r"(a1), "r"(a2), "r"(a3), "r"(b0), "r"(b1));
}
#define LDSM4T(r0, r1, r2, r3, addr) \
    asm volatile("ldmatrix.sync.aligned.m8n8.x4.trans.shared.b16 {%0,%1,%2,%3}, [%4];" \
                 : "=r"(r0), "=r"(r1), "=r"(r2), "=r"(r3) : "r"(addr))

__device__ __forceinline__ void cp16(void* smem, const void* gmem) {
    uint32_t s = (uint32_t)__cvta_generic_to_shared(smem);
    asm volatile("cp.async.cg.shared.global [%0], [%1], 16;\n" :: "r"(s), "l"(gmem));
}
__device__ __forceinline__ void cp_commit() { asm volatile("cp.async.commit_group;\n"); }
__device__ __forceinline__ void cp_wait0() { asm volatile("cp.async.wait_group 0;\n"); }
__device__ __forceinline__ void cp_wait1() { asm volatile("cp.async.wait_group 1;\n"); }

// ---------------------------------------------------------------------------
// Stage A (merged): per-head projections via fp16 mma + Wf->fp16 prepass.
// grid (6, 256, 4), block 256.  (exact R13 version)
// Q output scaled by log2e/sqrt(E) so attn softmax uses raw ex2.
// smem (halves): Xh[128][72] | Wh[64][72]  = 27648 B
// ---------------------------------------------------------------------------
#define PXH(r, c_) psm[(r) * 72 + (c_)]
#define PWH(r, c_) psm[9216 + (r) * 72 + (c_)]

__global__ __launch_bounds__(256) void proj_mma_kernel(
    const float* __restrict__ q, const float* __restrict__ k, const float* __restrict__ v,
    const float* __restrict__ Wq, const float* __restrict__ Wk, const float* __restrict__ Wv,
    const float* __restrict__ Wf)
{
    extern __shared__ __half psm[];
    const int which = blockIdx.z;
    const int tid = threadIdx.x;

    if (which == 3) {
        // Wf -> fp16, 8 elements per thread
        const int gid = (blockIdx.y * 6 + blockIdx.x) * 256 + tid;
        if (gid < EE * EE / 8) {
            const float4 v0 = *(const float4*)(Wf + (size_t)gid * 8);
            const float4 v1 = *(const float4*)(Wf + (size_t)gid * 8 + 4);
            __half2 h[4];
            h[0] = __floats2half2_rn(v0.x, v0.y);
            h[1] = __floats2half2_rn(v0.z, v0.w);
            h[2] = __floats2half2_rn(v1.x, v1.y);
            h[3] = __floats2half2_rn(v1.z, v1.w);
            *(float4*)(g_wtf + (size_t)gid * 8) = *(float4*)h;
        }
        return;
    }

    const float* X = (which == 0) ? q : (which == 1) ? k : v;
    const float* W = (which == 0) ? Wq : (which == 1) ? Wk : Wv;
    __half* Y = (which == 0) ? g_qh : (which == 1) ? g_kh : g_vh;
    const float oscl = (which == 0) ? (0.03125f * 1.44269504f) : 1.0f;

    const int bh = blockIdx.y;
    const int b = bh >> 4, h = bh & 15;
    const int n0 = blockIdx.x * 128;

    // stage X (128x64) and W (64x64) as fp16
    {
        const int rr = tid >> 4;
        const int c4 = (tid & 15) * 4;
        const float* src = X + ((size_t)b * NN + n0) * EE + h * DD;
        #pragma unroll
        for (int i = 0; i < 8; i++) {
            const int row = rr + 16 * i;
            float4 vv = *(const float4*)(src + (size_t)row * EE + c4);
            __half2 h2[2] = {__floats2half2_rn(vv.x, vv.y), __floats2half2_rn(vv.z, vv.w)};
            *(float2*)&PXH(row, c4) = *(float2*)h2;
        }
        const float* wsrc = W + h * DD * DD;
        #pragma unroll
        for (int i = 0; i < 4; i++) {
            const int row = rr + 16 * i;
            float4 wv = *(const float4*)(wsrc + row * DD + c4);
            __half2 h2[2] = {__floats2half2_rn(wv.x, wv.y), __floats2half2_rn(wv.z, wv.w)};
            *(float2*)&PWH(row, c4) = *(float2*)h2;
        }
    }
    __syncthreads();

    const int w = tid >> 5;
    const int lane = tid & 31;
    const int g = lane >> 2;
    const int qd = lane & 3;
    const int qrow = 16 * w + g;

    float acc[8][4] = {};
    #pragma unroll
    for (int kk = 0; kk < 4; kk++) {
        uint32_t a0 = *(uint32_t*)&PXH(qrow,     kk * 16 + 2 * qd);
        uint32_t a1 = *(uint32_t*)&PXH(qrow + 8, kk * 16 + 2 * qd);
        uint32_t a2 = *(uint32_t*)&PXH(qrow,     kk * 16 + 2 * qd + 8);
        uint32_t a3 = *(uint32_t*)&PXH(qrow + 8, kk * 16 + 2 * qd + 8);
        #pragma unroll
        for (int nt = 0; nt < 8; nt++) {
            uint32_t b0 = *(uint32_t*)&PWH(nt * 8 + g, kk * 16 + 2 * qd);
            uint32_t b1 = *(uint32_t*)&PWH(nt * 8 + g, kk * 16 + 2 * qd + 8);
            mma_f16(acc[nt], a0, a1, a2, a3, b0, b1);
        }
    }

    __half* dst = Y + (((size_t)bh) * NN + n0 + 16 * w) * DD;
    #pragma unroll
    for (int nt = 0; nt < 8; nt++) {
        const int col = nt * 8 + 2 * qd;
        *(__half2*)(dst + (size_t)g * DD + col) =
            __floats2half2_rn(acc[nt][0] * oscl, acc[nt][1] * oscl);
        *(__half2*)(dst + (size_t)(g + 8) * DD + col) =
            __floats2half2_rn(acc[nt][2] * oscl, acc[nt][3] * oscl);
    }
}

// ---------------------------------------------------------------------------
// Stage B: flash attention (exact R13 version), fp16 mma m16n8k16,
// ktile=64 sync staging, log2 softmax, deferred l-reduction,
// V B-frags via ldmatrix.trans; Q/K feeds scalar LDS.32.
// grid (6, 256), block 256, dynamic smem 39936 B, 2 CTAs/SM.
// smem (halves): Qs[128][72] | Ks[64][72] | Vs[64][72] | madd[768] (floats)
// ---------------------------------------------------------------------------
#define QH(r, c_) smh[(r) * 72 + (c_)]
#define KH(r, c_) smh[9216 + (r) * 72 + (c_)]
#define VH(r, c_) smh[13824 + (r) * 72 + (c_)]

__global__ __launch_bounds__(256, 2) void attn_f16_kernel(const float* __restrict__ mask)
{
    extern __shared__ __half smh[];
    float* madd = (float*)(smh + 18432);

    const int bh = blockIdx.y;
    const int b = bh >> 4, h = bh & 15;
    const int q0 = blockIdx.x * 128;
    const int tid = threadIdx.x;
    const int w = tid >> 5;
    const int lane = tid & 31;
    const int g = lane >> 2;
    const int qd = lane & 3;

    for (int i = tid; i < NN; i += 256)
        madd[i] = (mask[h * NN + i] == -INFINITY) ? NEGV2 : 0.f;

    const __half* qb = g_qh + ((size_t)bh * NN + q0) * DD;
    const __half* kb = g_kh + ((size_t)bh * NN) * DD;
    const __half* vb = g_vh + ((size_t)bh * NN) * DD;

    {
        const int rr = tid >> 3, c8 = (tid & 7) * 8;
        #pragma unroll
        for (int i = 0; i < 4; i++)
            *(float4*)&QH(rr + 32 * i, c8) =
                *(const float4*)(qb + (size_t)(rr + 32 * i) * DD + c8);
    }
    __syncthreads();

    const int qrow = 16 * w + g;
    const float addq0 = madd[q0 + qrow];
    const float addq1 = madd[q0 + qrow + 8];

    float m0r = -INFINITY, m1r = -INFINITY;
    float l0 = 0.f, l1 = 0.f;          // per-thread partials; reduced at end
    float o[8][4] = {};

    // ldmatrix.trans V address bases (k-rows x d-cols)
    const uint32_t smbh = (uint32_t)__cvta_generic_to_shared(smh);
    const int sq = lane >> 3, rp = lane & 7;
    uint32_t aV[4];
    #pragma unroll
    for (int dp = 0; dp < 4; dp++)
        aV[dp] = smbh + 2u * (13824 + ((sq & 1) * 8 + rp) * 72
                              + dp * 16 + (sq >> 1) * 8);

    for (int kt = 0; kt < NN; kt += 64) {
        __syncthreads();
        {
            const int rr = tid >> 3, c8 = (tid & 7) * 8;
            #pragma unroll
            for (int i = 0; i < 2; i++) {
                *(float4*)&KH(rr + 32 * i, c8) =
                    *(const float4*)(kb + (size_t)(kt + rr + 32 * i) * DD + c8);
                *(float4*)&VH(rr + 32 * i, c8) =
                    *(const float4*)(vb + (size_t)(kt + rr + 32 * i) * DD + c8);
            }
        }
        __syncthreads();

        // S = Q K^T
        float s[8][4] = {};
        #pragma unroll
        for (int kk = 0; kk < 4; kk++) {
            uint32_t a0 = *(uint32_t*)&QH(qrow,     kk * 16 + 2 * qd);
            uint32_t a1 = *(uint32_t*)&QH(qrow + 8, kk * 16 + 2 * qd);
            uint32_t a2 = *(uint32_t*)&QH(qrow,     kk * 16 + 2 * qd + 8);
            uint32_t a3 = *(uint32_t*)&QH(qrow + 8, kk * 16 + 2 * qd + 8);
            #pragma unroll
            for (int nt = 0; nt < 8; nt++) {
                uint32_t b0 = *(uint32_t*)&KH(nt * 8 + g, kk * 16 + 2 * qd);
                uint32_t b1 = *(uint32_t*)&KH(nt * 8 + g, kk * 16 + 2 * qd + 8);
                mma_f16(s[nt], a0, a1, a2, a3, b0, b1);
            }
        }

        // mask + online softmax (log2 domain); max must be quad-uniform
        float pm0 = -INFINITY, pm1 = -INFINITY;
        #pragma unroll
        for (int nt = 0; nt < 8; nt++) {
            float2 mk = *(const float2*)&madd[kt + nt * 8 + 2 * qd];
            s[nt][0] += fmaxf(addq0 + mk.x, NEGV2);
            s[nt][1] += fmaxf(addq0 + mk.y, NEGV2);
            s[nt][2] += fmaxf(addq1 + mk.x, NEGV2);
            s[nt][3] += fmaxf(addq1 + mk.y, NEGV2);
            pm0 = fmaxf(pm0, fmaxf(s[nt][0], s[nt][1]));
            pm1 = fmaxf(pm1, fmaxf(s[nt][2], s[nt][3]));
        }
        pm0 = fmaxf(pm0, __shfl_xor_sync(0xffffffffu, pm0, 1));
        pm0 = fmaxf(pm0, __shfl_xor_sync(0xffffffffu, pm0, 2));
        pm1 = fmaxf(pm1, __shfl_xor_sync(0xffffffffu, pm1, 1));
        pm1 = fmaxf(pm1, __shfl_xor_sync(0xffffffffu, pm1, 2));

        const float mn0 = fmaxf(m0r, pm0), mn1 = fmaxf(m1r, pm1);
        const float corr0 = ex2(m0r - mn0), corr1 = ex2(m1r - mn1);
        m0r = mn0; m1r = mn1;

        float rs0 = 0.f, rs1 = 0.f;
        #pragma unroll
        for (int nt = 0; nt < 8; nt++) {
            s[nt][0] = ex2(s[nt][0] - mn0); rs0 += s[nt][0];
            s[nt][1] = ex2(s[nt][1] - mn0); rs0 += s[nt][1];
            s[nt][2] = ex2(s[nt][2] - mn1); rs1 += s[nt][2];
            s[nt][3] = ex2(s[nt][3] - mn1); rs1 += s[nt][3];
        }
        l0 = l0 * corr0 + rs0;
        l1 = l1 * corr1 + rs1;

        #pragma unroll
        for (int dt = 0; dt < 8; dt++) {
            o[dt][0] *= corr0; o[dt][1] *= corr0;
            o[dt][2] *= corr1; o[dt][3] *= corr1;
        }

        // pack P C-fragments into A-fragments (direct register feed)
        uint32_t ph[8][2];
        #pragma unroll
        for (int nt = 0; nt < 8; nt++) {
            ph[nt][0] = pack2(s[nt][0], s[nt][1]);
            ph[nt][1] = pack2(s[nt][2], s[nt][3]);
        }

        // O += P V  (V B-fragments via ldmatrix.x4.trans)
        #pragma unroll
        for (int kk = 0; kk < 4; kk++) {
            uint32_t a0 = ph[2 * kk][0];
            uint32_t a1 = ph[2 * kk][1];
            uint32_t a2 = ph[2 * kk + 1][0];
            uint32_t a3 = ph[2 * kk + 1][1];
            #pragma unroll
            for (int dp = 0; dp < 4; dp++) {
                uint32_t b0, b1, b2, b3;
                LDSM4T(b0, b1, b2, b3, aV[dp] + kk * 2304u);
                mma_f16(o[2 * dp],     a0, a1, a2, a3, b0, b1);
                mma_f16(o[2 * dp + 1], a0, a1, a2, a3, b2, b3);
            }
        }
    }

    // final quad reduction of l partials
    l0 += __shfl_xor_sync(0xffffffffu, l0, 1);
    l0 += __shfl_xor_sync(0xffffffffu, l0, 2);
    l1 += __shfl_xor_sync(0xffffffffu, l1, 1);
    l1 += __shfl_xor_sync(0xffffffffu, l1, 2);

    const float inv0 = 1.f / l0, inv1 = 1.f / l1;
    __half* ob = g_attn + ((size_t)b * NN + q0 + 16 * w) * EE + h * DD;
    #pragma unroll
    for (int dt = 0; dt < 8; dt++) {
        const int col = dt * 8 + 2 * qd;
        *(__half2*)(ob + (size_t)g * EE + col) =
            __floats2half2_rn(o[dt][0] * inv0, o[dt][1] * inv0);
        *(__half2*)(ob + (size_t)(g + 8) * EE + col) =
            __floats2half2_rn(o[dt][2] * inv1, o[dt][3] * inv1);
    }
}

// ---------------------------------------------------------------------------
// Stage C: out = g_attn @ Wf^T, fp16 mma m16n8k16. 128x128x64(halves) chunks,
// THREE-stage cp.async pipeline (wait_group 1 keeps one load in flight).
// grid (8, 96), block 256, smem 110592 B, 2 CTAs/SM.
// smem (halves): As[3][128][72] | Ws[3][128][72]
// ---------------------------------------------------------------------------
#define ASH(bf, r, c_) smh[(bf) * 9216 + (r) * 72 + (c_)]
#define WSH(bf, r, c_) smh[27648 + (bf) * 9216 + (r) * 72 + (c_)]

__global__ __launch_bounds__(256, 2) void gemm_f16_kernel(float* __restrict__ out)
{
    extern __shared__ __half smh[];

    const int e0 = blockIdx.x * 128;
    const int m0 = blockIdx.y * 128;
    const int tid = threadIdx.x;
    const int w = tid >> 5;
    const int lane = tid & 31;
    const int g = lane >> 2, qd = lane & 3;
    const int mb = (w & 1) * 64;
    const int nb = (w >> 1) * 32;

    const __half* Ab = g_attn + (size_t)m0 * EE;
    const __half* Wb = g_wtf + (size_t)e0 * EE;

    const int rr = tid >> 3;           // 0..31
    const int c8 = (tid & 7) * 8;      // half col of 16B piece

    float acc[4][4][4] = {};

    // stage chunk `it` into buffer `bf`
    auto stage = [&](int it, int bf) {
        const int kc = it * 64;
        #pragma unroll
        for (int i = 0; i < 4; i++) {
            cp16(&ASH(bf, rr + 32 * i, c8), Ab + (size_t)(rr + 32 * i) * EE + kc + c8);
            cp16(&WSH(bf, rr + 32 * i, c8), Wb + (size_t)(rr + 32 * i) * EE + kc + c8);
        }
    };

    stage(0, 0); cp_commit();
    stage(1, 1); cp_commit();

    const int NCH = EE / 64;   // 16
    for (int it = 0; it < NCH; it++) {
        const int buf = it % 3;
        if (it + 2 < NCH) cp_wait1(); else cp_wait0();
        __syncthreads();

        if (it + 2 < NCH) {
            stage(it + 2, (it + 2) % 3);
            cp_commit();
        }

        #pragma unroll
        for (int kk = 0; kk < 4; kk++) {
            uint32_t a[4][4];
            #pragma unroll
            for (int mt = 0; mt < 4; mt++) {
                const int row = mb + mt * 16 + g;
                a[mt][0] = *(uint32_t*)&ASH(buf, row,     kk * 16 + 2 * qd);
                a[mt][1] = *(uint32_t*)&ASH(buf, row + 8, kk * 16 + 2 * qd);
                a[mt][2] = *(uint32_t*)&ASH(buf, row,     kk * 16 + 2 * qd + 8);
                a[mt][3] = *(uint32_t*)&ASH(buf, row + 8, kk * 16 + 2 * qd + 8);
            }
            #pragma unroll
            for (int nt = 0; nt < 4; nt++) {
                uint32_t b0 = *(uint32_t*)&WSH(buf, nb + nt * 8 + g, kk * 16 + 2 * qd);
                uint32_t b1 = *(uint32_t*)&WSH(buf, nb + nt * 8 + g, kk * 16 + 2 * qd + 8);
                #pragma unroll
                for (int mt = 0; mt < 4; mt++)
                    mma_f16(acc[mt][nt], a[mt][0], a[mt][1], a[mt][2], a[mt][3], b0, b1);
            }
        }
    }

    #pragma unroll
    for (int mt = 0; mt < 4; mt++) {
        const int row0 = m0 + mb + mt * 16 + g;
        #pragma unroll
        for (int nt = 0; nt < 4; nt++) {
            const int col = e0 + nb + nt * 8 + 2 * qd;
            *(float2*)(out + (size_t)row0 * EE + col) =
                make_float2(acc[mt][nt][0], acc[mt][nt][1]);
            *(float2*)(out + (size_t)(row0 + 8) * EE + col) =
                make_float2(acc[mt][nt][2], acc[mt][nt][3]);
        }
    }
}

// ---------------------------------------------------------------------------
extern "C" void kernel_launch(void* const* d_in, const int* in_sizes, int n_in,
                              void* d_out, int out_size)
{
    const float* q    = (const float*)d_in[0];
    const float* k    = (const float*)d_in[1];
    const float* v    = (const float*)d_in[2];
    const float* mask = (const float*)d_in[3];
    const float* Wq   = (const float*)d_in[4];
    const float* Wk   = (const float*)d_in[5];
    const float* Wv   = (const float*)d_in[6];
    const float* Wf   = (const float*)d_in[7];
    float* out = (float*)d_out;

    const int proj_smem = (128 * 72 + 64 * 72) * 2;   // 27648
    const int attn_smem = 18432 * 2 + 768 * 4;        // 39936
    const int gemm_smem = 55296 * 2;                  // 110592
    cudaFuncSetAttribute(proj_mma_kernel,
                         cudaFuncAttributeMaxDynamicSharedMemorySize, proj_smem);
    cudaFuncSetAttribute(attn_f16_kernel,
                         cudaFuncAttributeMaxDynamicSharedMemorySize, attn_smem);
    cudaFuncSetAttribute(gemm_f16_kernel,
                         cudaFuncAttributeMaxDynamicSharedMemorySize, gemm_smem);

    proj_mma_kernel<<<dim3(NN / 128, BB * HH, 4), 256, proj_smem>>>(
        q, k, v, Wq, Wk, Wv, Wf);
    attn_f16_kernel<<<dim3(NN / 128, BB * HH), 256, attn_smem>>>(mask);
    gemm_f16_kernel<<<dim3(EE / 128, (BB * NN) / 128), 256, gemm_smem>>>(out);
}